// round 4
// baseline (speedup 1.0000x reference)
#include <cuda_runtime.h>

#define BB 2048
#define LL 8192
#define GG 256
#define BETA 0.01f

// Precomputed label layout (recomputed every launch; __device__ globals = legal scratch).
__device__ int g_start[GG + 1];   // group segment offsets (exclusive prefix), g_start[GG] = LL
__device__ int g_dest[LL];        // PRE-SWIZZLED word slot in s_vals

// XOR swizzle on word index: segment reads in phase 2 become conflict-free,
// scatter stores stay random (expected low conflict). Bijective on [0, LL).
__device__ __forceinline__ int SW(int w) { return w ^ ((w >> 5) & 31); }

__global__ __launch_bounds__(256) void setup_kernel(const int* __restrict__ gid,
                                                    float* __restrict__ out)
{
    __shared__ int cnt[GG];
    __shared__ int cnt2[GG];
    __shared__ int start_s[GG];
    __shared__ int wsum[8];

    const int t = threadIdx.x;
    if (t == 0) out[0] = 0.0f;           // replaces cudaMemsetAsync node
    cnt[t] = 0;
    cnt2[t] = 0;
    __syncthreads();

    #pragma unroll
    for (int i = t; i < LL; i += 256)
        atomicAdd(&cnt[gid[i]], 1);
    __syncthreads();

    // Exclusive prefix sum over 256 counts.
    const int lane = t & 31, wid = t >> 5;
    const int v = cnt[t];
    int s = v;
    #pragma unroll
    for (int o = 1; o < 32; o <<= 1) {
        int u = __shfl_up_sync(0xffffffffu, s, o);
        if (lane >= o) s += u;
    }
    if (lane == 31) wsum[wid] = s;
    __syncthreads();
    int off = 0;
    #pragma unroll
    for (int w = 0; w < 8; w++)
        if (w < wid) off += wsum[w];
    const int excl = off + s - v;
    start_s[t] = excl;
    g_start[t] = excl;
    if (t == 255) g_start[GG] = LL;
    __syncthreads();

    #pragma unroll
    for (int i = t; i < LL; i += 256) {
        const int g = gid[i];
        const int r = atomicAdd(&cnt2[g], 1);
        g_dest[i] = SW(start_s[g] + r);   // final swizzled slot, no hot-loop math
    }
}

__global__ __launch_bounds__(256) void meta_row_kernel(
    const float* __restrict__ logits,
    const int*   __restrict__ true_y,
    float*       __restrict__ out)
{
    __shared__ int   s_vals[LL];   // 32 KB; value with any_true flag packed in bit0
    __shared__ float s_red[8];

    const int tid = threadIdx.x;
    const int row = blockIdx.x;

    const float4* lg4 = (const float4*)(logits + (size_t)row * LL);
    const int4*   ty4 = (const int4*)(true_y + (size_t)row * LL);
    const int4*   dd4 = (const int4*)g_dest;

    #pragma unroll
    for (int i = 0; i < 8; i++) {
        const int idx = tid + 256 * i;
        const float4 x = lg4[idx];
        const int4   y = ty4[idx];   // values are exactly 0 or 1
        const int4   d = dd4[idx];

        // log_sigmoid(-x) = -softplus(x) = -(max(x,0) + log(1 + exp(-|x|)))
        const float v0 = -(fmaxf(x.x, 0.0f) + __logf(1.0f + __expf(-fabsf(x.x))));
        const float v1 = -(fmaxf(x.y, 0.0f) + __logf(1.0f + __expf(-fabsf(x.y))));
        const float v2 = -(fmaxf(x.z, 0.0f) + __logf(1.0f + __expf(-fabsf(x.z))));
        const float v3 = -(fmaxf(x.w, 0.0f) + __logf(1.0f + __expf(-fabsf(x.w))));

        // Pack any_true flag into mantissa bit0 (<=2^-23 rel perturbation).
        s_vals[d.x] = (__float_as_int(v0) & ~1) | y.x;
        s_vals[d.y] = (__float_as_int(v1) & ~1) | y.y;
        s_vals[d.z] = (__float_as_int(v2) & ~1) | y.z;
        s_vals[d.w] = (__float_as_int(v3) & ~1) | y.w;
    }
    __syncthreads();

    // Phase 2: thread g reduces its group's contiguous (swizzled) segment.
    const int st = g_start[tid];
    const int en = g_start[tid + 1];
    int   fl = 0;
    float gl = 0.0f;
    for (int i = st; i < en; i++) {
        const int u = s_vals[SW(i)];
        fl |= u;
        gl += __int_as_float(u);
    }

    float term;
    if (fl & 1) {
        term = fmaxf(gl, -100.0f);                    // meta_y = 1
    } else {
        const float em = expm1f(gl);                  // accurate log(1 - exp(gl))
        term = fmaxf(logf(fmaxf(-em, 1e-45f)), -100.0f);
    }

    // Block reduction, then one atomic per row into the scalar output.
    #pragma unroll
    for (int o = 16; o > 0; o >>= 1)
        term += __shfl_xor_sync(0xffffffffu, term, o);
    if ((tid & 31) == 0) s_red[tid >> 5] = term;
    __syncthreads();
    if (tid < 8) {
        float v = s_red[tid];
        #pragma unroll
        for (int o = 4; o > 0; o >>= 1)
            v += __shfl_xor_sync(0x000000ffu, v, o);
        if (tid == 0)
            atomicAdd(out, v * (-BETA / (float)(BB * GG)));
    }
}

extern "C" void kernel_launch(void* const* d_in, const int* in_sizes, int n_in,
                              void* d_out, int out_size)
{
    const float* logits    = (const float*)d_in[0];
    const int*   true_y    = (const int*)d_in[1];
    const int*   group_ids = (const int*)d_in[2];
    float* out = (float*)d_out;

    setup_kernel<<<1, 256>>>(group_ids, out);
    meta_row_kernel<<<BB, 256>>>(logits, true_y, out);
}